// round 1
// baseline (speedup 1.0000x reference)
#include <cuda_runtime.h>
#include <cuda_bf16.h>

#define NX 2048
#define NY 4096

// Coefficient tables (scratch via __device__ globals — no allocations allowed).
// Layout: float4 per index: (a, b, c, unused) for d1 and d2 separately.
__device__ float4 g_c1y[NY];
__device__ float4 g_c2y[NY];
__device__ float4 g_c1x[NX];
__device__ float4 g_c2x[NX];

// Compute the 3-tap first/second derivative coefficients at index idx of a
// nonuniform grid g[0..n-1]. Boundary points use one-sided stencils over
// {0,1,2} / {n-3,n-2,n-1}; interior uses {idx-1, idx, idx+1}. The stencil
// base in the main kernel is clamp(idx-1, 0, n-3), so the coefficient order
// here matches taps (base, base+1, base+2).
__device__ __forceinline__ void deriv_coeffs(const float* __restrict__ g, int n, int idx,
                                             float4& d1, float4& d2) {
    if (idx == 0) {
        float hA = g[1] - g[0];
        float hB = g[2] - g[1];
        d1.x = -(2.0f * hA + hB) / (hA * (hA + hB));
        d1.y = (hA + hB) / (hA * hB);
        d1.z = -hA / (hB * (hA + hB));
        d2.x = 2.0f / (hA * (hA + hB));
        d2.y = -2.0f / (hA * hB);
        d2.z = 2.0f / (hB * (hA + hB));
    } else if (idx == n - 1) {
        float hC = g[n - 2] - g[n - 3];
        float hD = g[n - 1] - g[n - 2];
        d1.x = hD / (hC * (hC + hD));
        d1.y = -(hC + hD) / (hC * hD);
        d1.z = (hC + 2.0f * hD) / (hD * (hC + hD));
        d2.x = 2.0f / (hC * (hC + hD));
        d2.y = -2.0f / (hC * hD);
        d2.z = 2.0f / (hD * (hC + hD));
    } else {
        float h1 = g[idx] - g[idx - 1];
        float h2 = g[idx + 1] - g[idx];
        d1.x = -h2 / (h1 * (h1 + h2));
        d1.y = (h2 - h1) / (h1 * h2);
        d1.z = h1 / (h2 * (h1 + h2));
        d2.x = 2.0f / (h1 * (h1 + h2));
        d2.y = -2.0f / (h1 * h2);
        d2.z = 2.0f / (h2 * (h1 + h2));
    }
    d1.w = 0.0f;
    d2.w = 0.0f;
}

__global__ void coeff_kernel(const float* __restrict__ x, const float* __restrict__ y) {
    int t = blockIdx.x * blockDim.x + threadIdx.x;
    if (t < NY) {
        float4 d1, d2;
        deriv_coeffs(y, NY, t, d1, d2);
        g_c1y[t] = d1;
        g_c2y[t] = d2;
    } else if (t < NY + NX) {
        int i = t - NY;
        float4 d1, d2;
        deriv_coeffs(x, NX, i, d1, d2);
        g_c1x[i] = d1;
        g_c2x[i] = d2;
    }
}

__global__ __launch_bounds__(128) void rhs_kernel(const float* __restrict__ state,
                                                  const float* __restrict__ mu_p,
                                                  float* __restrict__ out) {
    const int j = blockIdx.x * blockDim.x + threadIdx.x;
    const int i = blockIdx.y;
    if (j >= NY) return;

    const float* __restrict__ u = state;
    const float* __restrict__ v = state + (size_t)NX * NY;

    // Unified stencil bases (boundary one-sided stencils read {0,1,2} or {n-3..n-1})
    const int bj = min(max(j - 1, 0), NY - 3);
    const int bi = min(max(i - 1, 0), NX - 3);

    const float mu = mu_p[0];

    const size_t row = (size_t)i * NY;

    // y-direction taps (contiguous; ±1 element → same cache lines)
    const float uy0 = __ldg(&u[row + bj]);
    const float uy1 = __ldg(&u[row + bj + 1]);
    const float uy2 = __ldg(&u[row + bj + 2]);
    const float vy0 = __ldg(&v[row + bj]);
    const float vy1 = __ldg(&v[row + bj + 1]);
    const float vy2 = __ldg(&v[row + bj + 2]);

    // x-direction taps (coalesced rows, re-used across adjacent blockIdx.y via L2)
    const float ux0 = __ldg(&u[(size_t)bi * NY + j]);
    const float ux1 = __ldg(&u[(size_t)(bi + 1) * NY + j]);
    const float ux2 = __ldg(&u[(size_t)(bi + 2) * NY + j]);
    const float vx0 = __ldg(&v[(size_t)bi * NY + j]);
    const float vx1 = __ldg(&v[(size_t)(bi + 1) * NY + j]);
    const float vx2 = __ldg(&v[(size_t)(bi + 2) * NY + j]);

    // Center values for the advection velocities (cache hits)
    const float uc = __ldg(&u[row + j]);
    const float vc = __ldg(&v[row + j]);

    // Coefficients
    const float4 c1y = g_c1y[j];
    const float4 c2y = g_c2y[j];
    const float4 c1x = g_c1x[i];
    const float4 c2x = g_c2x[i];

    const float d1y_u = c1y.x * uy0 + c1y.y * uy1 + c1y.z * uy2;
    const float d2y_u = c2y.x * uy0 + c2y.y * uy1 + c2y.z * uy2;
    const float d1y_v = c1y.x * vy0 + c1y.y * vy1 + c1y.z * vy2;
    const float d2y_v = c2y.x * vy0 + c2y.y * vy1 + c2y.z * vy2;

    const float d1x_u = c1x.x * ux0 + c1x.y * ux1 + c1x.z * ux2;
    const float d2x_u = c2x.x * ux0 + c2x.y * ux1 + c2x.z * ux2;
    const float d1x_v = c1x.x * vx0 + c1x.y * vx1 + c1x.z * vx2;
    const float d2x_v = c2x.x * vx0 + c2x.y * vx1 + c2x.z * vx2;

    float du = mu * (d2y_u + d2x_u) - uc * d1x_u - vc * d1y_u + 0.01f;
    float dv = mu * (d2y_v + d2x_v) - uc * d1x_v - vc * d1y_v;

    // Boundary conditions:
    //   du[:, -1] = du[:, 0] = du[0, :] = 0
    //   dv[:, 0] = dv[0, :] = 0
    if (j == 0 || j == NY - 1 || i == 0) du = 0.0f;
    if (j == 0 || i == 0) dv = 0.0f;

    out[row + j] = du;
    out[(size_t)NX * NY + row + j] = dv;
}

// Inputs (metadata order): t[1], state[2*NX*NY], x[NX], y[NY], mu[1]
extern "C" void kernel_launch(void* const* d_in, const int* in_sizes, int n_in,
                              void* d_out, int out_size) {
    const float* state = (const float*)d_in[1];
    const float* x     = (const float*)d_in[2];
    const float* y     = (const float*)d_in[3];
    const float* mu    = (const float*)d_in[4];
    float* out = (float*)d_out;

    // Prologue: fill coefficient tables (NX + NY = 6144 indices)
    {
        int total = NX + NY;
        int threads = 128;
        int blocks = (total + threads - 1) / threads;
        coeff_kernel<<<blocks, threads>>>(x, y);
    }

    // Main RHS kernel: 128 threads along contiguous j, one row per blockIdx.y
    {
        dim3 block(128, 1, 1);
        dim3 grid(NY / 128, NX, 1);
        rhs_kernel<<<grid, block>>>(state, mu, out);
    }
}

// round 2
// speedup vs baseline: 1.0006x; 1.0006x over previous
#include <cuda_runtime.h>
#include <cuda_bf16.h>

#define NX 2048
#define NY 4096

// Coefficient tables (__device__ globals — allocations are forbidden).
// y-direction: SoA so 4 consecutive j load as one float4 each.
// d2 tables are PREMULTIPLIED BY MU at build time.
__device__ float g_c1ya[NY], g_c1yb[NY], g_c1yc[NY];
__device__ float g_c2ya[NY], g_c2yb[NY], g_c2yc[NY];
// x-direction: per-row, broadcast loads. (c2x premultiplied by mu.)
__device__ float4 g_c1x[NX];
__device__ float4 g_c2x[NX];

// 3-tap derivative coefficients at index idx of nonuniform grid g[0..n-1].
// Tap base convention: base = clamp(idx-1, 0, n-3); coefficients returned in
// tap order (base, base+1, base+2). Matches the reference's one-sided
// boundary stencils at idx==0 and idx==n-1.
__device__ __forceinline__ void deriv_coeffs(const float* __restrict__ g, int n, int idx,
                                             float3& d1, float3& d2) {
    if (idx == 0) {
        float hA = g[1] - g[0];
        float hB = g[2] - g[1];
        d1.x = -(2.0f * hA + hB) / (hA * (hA + hB));
        d1.y = (hA + hB) / (hA * hB);
        d1.z = -hA / (hB * (hA + hB));
        d2.x = 2.0f / (hA * (hA + hB));
        d2.y = -2.0f / (hA * hB);
        d2.z = 2.0f / (hB * (hA + hB));
    } else if (idx == n - 1) {
        float hC = g[n - 2] - g[n - 3];
        float hD = g[n - 1] - g[n - 2];
        d1.x = hD / (hC * (hC + hD));
        d1.y = -(hC + hD) / (hC * hD);
        d1.z = (hC + 2.0f * hD) / (hD * (hC + hD));
        d2.x = 2.0f / (hC * (hC + hD));
        d2.y = -2.0f / (hC * hD);
        d2.z = 2.0f / (hD * (hC + hD));
    } else {
        float h1 = g[idx] - g[idx - 1];
        float h2 = g[idx + 1] - g[idx];
        d1.x = -h2 / (h1 * (h1 + h2));
        d1.y = (h2 - h1) / (h1 * h2);
        d1.z = h1 / (h2 * (h1 + h2));
        d2.x = 2.0f / (h1 * (h1 + h2));
        d2.y = -2.0f / (h1 * h2);
        d2.z = 2.0f / (h2 * (h1 + h2));
    }
}

__global__ void coeff_kernel(const float* __restrict__ x, const float* __restrict__ y,
                             const float* __restrict__ mu_p) {
    const float mu = mu_p[0];
    int t = blockIdx.x * blockDim.x + threadIdx.x;
    if (t < NY) {
        float3 d1, d2;
        deriv_coeffs(y, NY, t, d1, d2);
        g_c1ya[t] = d1.x; g_c1yb[t] = d1.y; g_c1yc[t] = d1.z;
        g_c2ya[t] = mu * d2.x; g_c2yb[t] = mu * d2.y; g_c2yc[t] = mu * d2.z;
    } else if (t < NY + NX) {
        int i = t - NY;
        float3 d1, d2;
        deriv_coeffs(x, NX, i, d1, d2);
        g_c1x[i] = make_float4(d1.x, d1.y, d1.z, 0.0f);
        g_c2x[i] = make_float4(mu * d2.x, mu * d2.y, mu * d2.z, 0.0f);
    }
}

__device__ __forceinline__ float f4get(const float4& f, int k) {
    switch (k) { case 0: return f.x; case 1: return f.y; case 2: return f.z; default: return f.w; }
}

__global__ __launch_bounds__(128) void rhs_kernel(const float* __restrict__ state,
                                                  float* __restrict__ out) {
    const int j4 = (blockIdx.x * 128 + threadIdx.x) * 4;  // first of 4 j handled
    const int i = blockIdx.y;
    const int lane = threadIdx.x & 31;

    const float* __restrict__ u = state;
    const float* __restrict__ v = state + (size_t)NX * NY;
    const size_t row = (size_t)i * NY;

    // ---- center values (also the middle x-tap and the core y-taps) ----
    const float4 uc = __ldg((const float4*)(u + row + j4));
    const float4 vc = __ldg((const float4*)(v + row + j4));

    // ---- y halo via warp shuffle; warp-edge lanes fetch one scalar ----
    float uprev = __shfl_up_sync(0xffffffffu, uc.w, 1);
    float vprev = __shfl_up_sync(0xffffffffu, vc.w, 1);
    float unext = __shfl_down_sync(0xffffffffu, uc.x, 1);
    float vnext = __shfl_down_sync(0xffffffffu, vc.x, 1);
    if (lane == 0 && j4 > 0) {
        uprev = __ldg(u + row + j4 - 1);
        vprev = __ldg(v + row + j4 - 1);
    }
    if (lane == 31 && j4 + 4 < NY) {
        unext = __ldg(u + row + j4 + 4);
        vnext = __ldg(v + row + j4 + 4);
    }

    // ---- x taps: one of the 3 rows is always the center row; load other 2 ----
    const int bi = min(max(i - 1, 0), NX - 3);
    const int rA = (i == 0) ? 1 : bi;
    const int rB = (i == NX - 1) ? (NX - 2) : (bi + 2);
    const float4 uxA = __ldg((const float4*)(u + (size_t)rA * NY + j4));
    const float4 uxB = __ldg((const float4*)(u + (size_t)rB * NY + j4));
    const float4 vxA = __ldg((const float4*)(v + (size_t)rA * NY + j4));
    const float4 vxB = __ldg((const float4*)(v + (size_t)rB * NY + j4));

    const bool i_lo = (i == 0), i_hi = (i == NX - 1);
    const float4 ux0 = i_lo ? uc : uxA;
    const float4 ux1 = i_lo ? uxA : (i_hi ? uxB : uc);
    const float4 ux2 = i_hi ? uc : uxB;
    const float4 vx0 = i_lo ? vc : vxA;
    const float4 vx1 = i_lo ? vxA : (i_hi ? vxB : vc);
    const float4 vx2 = i_hi ? vc : vxB;

    // ---- coefficients ----
    const float4 c1a = __ldg((const float4*)(g_c1ya + j4));
    const float4 c1b = __ldg((const float4*)(g_c1yb + j4));
    const float4 c1c = __ldg((const float4*)(g_c1yc + j4));
    const float4 c2a = __ldg((const float4*)(g_c2ya + j4));  // mu-folded
    const float4 c2b = __ldg((const float4*)(g_c2yb + j4));
    const float4 c2c = __ldg((const float4*)(g_c2yc + j4));
    const float4 c1x = g_c1x[i];
    const float4 c2x = g_c2x[i];  // mu-folded

    const float ur[6] = { uprev, uc.x, uc.y, uc.z, uc.w, unext };
    const float vr[6] = { vprev, vc.x, vc.y, vc.z, vc.w, vnext };

    float4 du4, dv4;
    float* dup = &du4.x;
    float* dvp = &dv4.x;

#pragma unroll
    for (int k = 0; k < 4; ++k) {
        // y-taps for point j4+k: normally (ur[k], ur[k+1], ur[k+2]).
        // j==0 uses taps {0,1,2}=(uc.x,uc.y,uc.z); j==NY-1 uses {NY-3..NY-1}=(uc.y,uc.z,uc.w).
        int t0 = k, t1 = k + 1, t2 = k + 2;
        if (k == 0 && j4 == 0) { t0 = 1; t1 = 2; t2 = 3; }
        if (k == 3 && j4 + 4 == NY) { t0 = 2; t1 = 3; t2 = 4; }
        const float uL = ur[t0], uC = ur[t1], uR = ur[t2];
        const float vL = vr[t0], vC = vr[t1], vR = vr[t2];

        const float c1ak = f4get(c1a, k), c1bk = f4get(c1b, k), c1ck = f4get(c1c, k);
        const float c2ak = f4get(c2a, k), c2bk = f4get(c2b, k), c2ck = f4get(c2c, k);

        const float d1y_u = c1ak * uL + c1bk * uC + c1ck * uR;
        const float d1y_v = c1ak * vL + c1bk * vC + c1ck * vR;
        const float md2y_u = c2ak * uL + c2bk * uC + c2ck * uR;   // mu*d2y(u)
        const float md2y_v = c2ak * vL + c2bk * vC + c2ck * vR;

        const float u0 = f4get(ux0, k), u1 = f4get(ux1, k), u2 = f4get(ux2, k);
        const float v0 = f4get(vx0, k), v1 = f4get(vx1, k), v2 = f4get(vx2, k);

        const float d1x_u = c1x.x * u0 + c1x.y * u1 + c1x.z * u2;
        const float d1x_v = c1x.x * v0 + c1x.y * v1 + c1x.z * v2;
        const float md2x_u = c2x.x * u0 + c2x.y * u1 + c2x.z * u2;  // mu*d2x(u)
        const float md2x_v = c2x.x * v0 + c2x.y * v1 + c2x.z * v2;

        const float uck = f4get(uc, k);
        const float vck = f4get(vc, k);

        dup[k] = md2y_u + md2x_u - uck * d1x_u - vck * d1y_u + 0.01f;
        dvp[k] = md2y_v + md2x_v - uck * d1x_v - vck * d1y_v;
    }

    // Boundary conditions:
    //   du[:, 0] = du[:, -1] = du[0, :] = 0 ; dv[:, 0] = dv[0, :] = 0
    if (i == 0) { du4 = make_float4(0.f, 0.f, 0.f, 0.f); dv4 = make_float4(0.f, 0.f, 0.f, 0.f); }
    if (j4 == 0) { du4.x = 0.0f; dv4.x = 0.0f; }
    if (j4 + 4 == NY) { du4.w = 0.0f; }

    *(float4*)(out + row + j4) = du4;
    *(float4*)(out + (size_t)NX * NY + row + j4) = dv4;
}

// Inputs (metadata order): t[1], state[2*NX*NY], x[NX], y[NY], mu[1]
extern "C" void kernel_launch(void* const* d_in, const int* in_sizes, int n_in,
                              void* d_out, int out_size) {
    const float* state = (const float*)d_in[1];
    const float* x     = (const float*)d_in[2];
    const float* y     = (const float*)d_in[3];
    const float* mu    = (const float*)d_in[4];
    float* out = (float*)d_out;

    // Prologue: coefficient tables (NX + NY = 6144 indices)
    {
        int total = NX + NY;
        int threads = 128;
        int blocks = (total + threads - 1) / threads;
        coeff_kernel<<<blocks, threads>>>(x, y, mu);
    }

    // Main RHS kernel: each thread computes 4 consecutive j (float4 path).
    {
        dim3 block(128, 1, 1);
        dim3 grid(NY / 512, NX, 1);  // 8 x 2048 blocks
        rhs_kernel<<<grid, block>>>(state, out);
    }
}

// round 3
// speedup vs baseline: 1.3570x; 1.3562x over previous
#include <cuda_runtime.h>
#include <cuda_bf16.h>

#define NX 2048
#define NY 4096

// Coefficient tables (__device__ globals — allocations are forbidden).
// y-direction: SoA so 4 consecutive j load as one float4 each. d2 tables are
// premultiplied by mu.
__device__ float g_c1ya[NY], g_c1yb[NY], g_c1yc[NY];
__device__ float g_c2ya[NY], g_c2yb[NY], g_c2yc[NY];
// x-direction: PERMUTED to tap order (rowA, rowB, centerRow) so the hot kernel
// needs no row-selection logic. d2 premultiplied by mu.
//   interior i : rowA=i-1, rowB=i+1, center=i      -> (a, c, b)
//   i == 0     : rowA=1,   rowB=2,   center=0      -> (b, c, a)
//   i == NX-1  : rowA=NX-3,rowB=NX-2,center=NX-1   -> (a, b, c)
__device__ float4 g_cx1[NX];
__device__ float4 g_cx2[NX];

// 3-tap derivative coefficients at index idx of nonuniform grid g[0..n-1], in
// stencil-point order (a=lowest tap, b=middle, c=highest). Boundary points use
// the reference's one-sided stencils over {0,1,2} / {n-3,n-2,n-1}.
__device__ __forceinline__ void deriv_coeffs(const float* __restrict__ g, int n, int idx,
                                             float3& d1, float3& d2) {
    if (idx == 0) {
        float hA = g[1] - g[0];
        float hB = g[2] - g[1];
        d1.x = -(2.0f * hA + hB) / (hA * (hA + hB));
        d1.y = (hA + hB) / (hA * hB);
        d1.z = -hA / (hB * (hA + hB));
        d2.x = 2.0f / (hA * (hA + hB));
        d2.y = -2.0f / (hA * hB);
        d2.z = 2.0f / (hB * (hA + hB));
    } else if (idx == n - 1) {
        float hC = g[n - 2] - g[n - 3];
        float hD = g[n - 1] - g[n - 2];
        d1.x = hD / (hC * (hC + hD));
        d1.y = -(hC + hD) / (hC * hD);
        d1.z = (hC + 2.0f * hD) / (hD * (hC + hD));
        d2.x = 2.0f / (hC * (hC + hD));
        d2.y = -2.0f / (hC * hD);
        d2.z = 2.0f / (hD * (hC + hD));
    } else {
        float h1 = g[idx] - g[idx - 1];
        float h2 = g[idx + 1] - g[idx];
        d1.x = -h2 / (h1 * (h1 + h2));
        d1.y = (h2 - h1) / (h1 * h2);
        d1.z = h1 / (h2 * (h1 + h2));
        d2.x = 2.0f / (h1 * (h1 + h2));
        d2.y = -2.0f / (h1 * h2);
        d2.z = 2.0f / (h2 * (h1 + h2));
    }
}

__global__ void coeff_kernel(const float* __restrict__ x, const float* __restrict__ y,
                             const float* __restrict__ mu_p) {
    const float mu = mu_p[0];
    int t = blockIdx.x * blockDim.x + threadIdx.x;
    if (t < NY) {
        float3 d1, d2;
        deriv_coeffs(y, NY, t, d1, d2);
        g_c1ya[t] = d1.x; g_c1yb[t] = d1.y; g_c1yc[t] = d1.z;
        g_c2ya[t] = mu * d2.x; g_c2yb[t] = mu * d2.y; g_c2yc[t] = mu * d2.z;
    } else if (t < NY + NX) {
        int i = t - NY;
        float3 d1, d2;
        deriv_coeffs(x, NX, i, d1, d2);
        float4 p1, p2;  // permuted: (coeff_rowA, coeff_rowB, coeff_center, 0)
        if (i == 0) {
            p1 = make_float4(d1.y, d1.z, d1.x, 0.f);
            p2 = make_float4(d2.y, d2.z, d2.x, 0.f);
        } else if (i == NX - 1) {
            p1 = make_float4(d1.x, d1.y, d1.z, 0.f);
            p2 = make_float4(d2.x, d2.y, d2.z, 0.f);
        } else {
            p1 = make_float4(d1.x, d1.z, d1.y, 0.f);
            p2 = make_float4(d2.x, d2.z, d2.y, 0.f);
        }
        g_cx1[i] = p1;
        g_cx2[i] = make_float4(mu * p2.x, mu * p2.y, mu * p2.z, 0.f);
    }
}

__global__ __launch_bounds__(128) void rhs_kernel(const float* __restrict__ state,
                                                  float* __restrict__ out) {
    const int j4 = (blockIdx.x * 128 + threadIdx.x) * 4;  // first of 4 j handled
    const int i = blockIdx.y;
    const int lane = threadIdx.x & 31;

    const float* __restrict__ u = state;
    const float* __restrict__ v = state + (size_t)NX * NY;
    const size_t row = (size_t)i * NY;

    // ---- center values (middle x-tap and core y-taps) ----
    const float4 uc = __ldg((const float4*)(u + row + j4));
    const float4 vc = __ldg((const float4*)(v + row + j4));

    // ---- y halo via warp shuffle; warp-edge lanes fetch one scalar ----
    float uprev = __shfl_up_sync(0xffffffffu, uc.w, 1);
    float vprev = __shfl_up_sync(0xffffffffu, vc.w, 1);
    float unext = __shfl_down_sync(0xffffffffu, uc.x, 1);
    float vnext = __shfl_down_sync(0xffffffffu, vc.x, 1);
    if (lane == 0 && j4 > 0) {
        uprev = __ldg(u + row + j4 - 1);
        vprev = __ldg(v + row + j4 - 1);
    }
    if (lane == 31 && j4 + 4 < NY) {
        unext = __ldg(u + row + j4 + 4);
        vnext = __ldg(v + row + j4 + 4);
    }

    // ---- x taps: rows A and B (center tap is uc/vc). Coeffs are permuted to
    // (rowA, rowB, center) order, so no data selects are needed. ----
    const int bi = min(max(i - 1, 0), NX - 3);
    const int rA = (i == 0) ? 1 : bi;
    const int rB = (i == NX - 1) ? (NX - 2) : (bi + 2);
    const float4 uxA = __ldg((const float4*)(u + (size_t)rA * NY + j4));
    const float4 uxB = __ldg((const float4*)(u + (size_t)rB * NY + j4));
    const float4 vxA = __ldg((const float4*)(v + (size_t)rA * NY + j4));
    const float4 vxB = __ldg((const float4*)(v + (size_t)rB * NY + j4));

    // ---- coefficients ----
    const float4 c1a = __ldg((const float4*)(g_c1ya + j4));
    const float4 c1b = __ldg((const float4*)(g_c1yb + j4));
    const float4 c1c = __ldg((const float4*)(g_c1yc + j4));
    const float4 c2a = __ldg((const float4*)(g_c2ya + j4));  // mu-folded
    const float4 c2b = __ldg((const float4*)(g_c2yb + j4));
    const float4 c2c = __ldg((const float4*)(g_c2yc + j4));
    const float4 cx1 = g_cx1[i];
    const float4 cx2 = g_cx2[i];  // mu-folded

    // ---- j-boundary tap shifts (only k=0 / k=3 affected; 12 SELs total) ----
    const bool jlo = (j4 == 0);
    const bool jhi = (j4 + 4 == NY);
    const float u0L = jlo ? uc.x : uprev, u0C = jlo ? uc.y : uc.x, u0R = jlo ? uc.z : uc.y;
    const float v0L = jlo ? vc.x : vprev, v0C = jlo ? vc.y : vc.x, v0R = jlo ? vc.z : vc.y;
    const float u3L = jhi ? uc.y : uc.z, u3C = jhi ? uc.z : uc.w, u3R = jhi ? uc.w : unext;
    const float v3L = jhi ? vc.y : vc.z, v3C = jhi ? vc.z : vc.w, v3R = jhi ? vc.w : vnext;

    float4 du4, dv4;

#define PT(cmp, uL, uC, uR, vL, vC, vR)                                          \
    do {                                                                         \
        const float d1yu = c1a.cmp * (uL) + c1b.cmp * (uC) + c1c.cmp * (uR);     \
        const float m2yu = c2a.cmp * (uL) + c2b.cmp * (uC) + c2c.cmp * (uR);     \
        const float d1yv = c1a.cmp * (vL) + c1b.cmp * (vC) + c1c.cmp * (vR);     \
        const float m2yv = c2a.cmp * (vL) + c2b.cmp * (vC) + c2c.cmp * (vR);     \
        const float d1xu = cx1.x * uxA.cmp + cx1.y * uxB.cmp + cx1.z * uc.cmp;   \
        const float m2xu = cx2.x * uxA.cmp + cx2.y * uxB.cmp + cx2.z * uc.cmp;   \
        const float d1xv = cx1.x * vxA.cmp + cx1.y * vxB.cmp + cx1.z * vc.cmp;   \
        const float m2xv = cx2.x * vxA.cmp + cx2.y * vxB.cmp + cx2.z * vc.cmp;   \
        du4.cmp = m2yu + m2xu - uc.cmp * d1xu - vc.cmp * d1yu + 0.01f;           \
        dv4.cmp = m2yv + m2xv - uc.cmp * d1xv - vc.cmp * d1yv;                   \
    } while (0)

    PT(x, u0L, u0C, u0R, v0L, v0C, v0R);
    PT(y, uc.x, uc.y, uc.z, vc.x, vc.y, vc.z);
    PT(z, uc.y, uc.z, uc.w, vc.y, vc.z, vc.w);
    PT(w, u3L, u3C, u3R, v3L, v3C, v3R);
#undef PT

    // Boundary conditions:
    //   du[:, 0] = du[:, -1] = du[0, :] = 0 ; dv[:, 0] = dv[0, :] = 0
    if (i == 0) { du4 = make_float4(0.f, 0.f, 0.f, 0.f); dv4 = make_float4(0.f, 0.f, 0.f, 0.f); }
    if (jlo) { du4.x = 0.0f; dv4.x = 0.0f; }
    if (jhi) { du4.w = 0.0f; }

    *(float4*)(out + row + j4) = du4;
    *(float4*)(out + (size_t)NX * NY + row + j4) = dv4;
}

// Inputs (metadata order): t[1], state[2*NX*NY], x[NX], y[NY], mu[1]
extern "C" void kernel_launch(void* const* d_in, const int* in_sizes, int n_in,
                              void* d_out, int out_size) {
    const float* state = (const float*)d_in[1];
    const float* x     = (const float*)d_in[2];
    const float* y     = (const float*)d_in[3];
    const float* mu    = (const float*)d_in[4];
    float* out = (float*)d_out;

    // Prologue: coefficient tables (NX + NY = 6144 indices)
    {
        int total = NX + NY;
        int threads = 128;
        int blocks = (total + threads - 1) / threads;
        coeff_kernel<<<blocks, threads>>>(x, y, mu);
    }

    // Main RHS kernel: each thread computes 4 consecutive j (float4 path).
    {
        dim3 block(128, 1, 1);
        dim3 grid(NY / 512, NX, 1);  // 8 x 2048 blocks
        rhs_kernel<<<grid, block>>>(state, out);
    }
}

// round 4
// speedup vs baseline: 1.4453x; 1.0651x over previous
#include <cuda_runtime.h>
#include <cuda_bf16.h>

#define NX 2048
#define NY 4096

// Coefficient tables (__device__ globals — allocations are forbidden).
// y-direction: SoA so 4 consecutive j load as one float4 each. d2 premult by mu.
__device__ float g_c1ya[NY], g_c1yb[NY], g_c1yc[NY];
__device__ float g_c2ya[NY], g_c2yb[NY], g_c2yc[NY];
// x-direction: PERMUTED to tap order (TA, TB, center):
//   interior i : TA=row i-1, TB=row i+1, center=i   -> coeffs (a, c, b)
//   i == 0     : TA=row 1,   TB=row 2,   center=0   -> coeffs (b, c, a)
//   i == NX-1  : TA=row NX-3,TB=row NX-2,center=NX-1-> coeffs (a, b, c)
__device__ float4 g_cx1[NX];
__device__ float4 g_cx2[NX];  // mu-folded

__device__ __forceinline__ void deriv_coeffs(const float* __restrict__ g, int n, int idx,
                                             float3& d1, float3& d2) {
    if (idx == 0) {
        float hA = g[1] - g[0];
        float hB = g[2] - g[1];
        d1.x = -(2.0f * hA + hB) / (hA * (hA + hB));
        d1.y = (hA + hB) / (hA * hB);
        d1.z = -hA / (hB * (hA + hB));
        d2.x = 2.0f / (hA * (hA + hB));
        d2.y = -2.0f / (hA * hB);
        d2.z = 2.0f / (hB * (hA + hB));
    } else if (idx == n - 1) {
        float hC = g[n - 2] - g[n - 3];
        float hD = g[n - 1] - g[n - 2];
        d1.x = hD / (hC * (hC + hD));
        d1.y = -(hC + hD) / (hC * hD);
        d1.z = (hC + 2.0f * hD) / (hD * (hC + hD));
        d2.x = 2.0f / (hC * (hC + hD));
        d2.y = -2.0f / (hC * hD);
        d2.z = 2.0f / (hD * (hC + hD));
    } else {
        float h1 = g[idx] - g[idx - 1];
        float h2 = g[idx + 1] - g[idx];
        d1.x = -h2 / (h1 * (h1 + h2));
        d1.y = (h2 - h1) / (h1 * h2);
        d1.z = h1 / (h2 * (h1 + h2));
        d2.x = 2.0f / (h1 * (h1 + h2));
        d2.y = -2.0f / (h1 * h2);
        d2.z = 2.0f / (h2 * (h1 + h2));
    }
}

__global__ void coeff_kernel(const float* __restrict__ x, const float* __restrict__ y,
                             const float* __restrict__ mu_p) {
    const float mu = mu_p[0];
    int t = blockIdx.x * blockDim.x + threadIdx.x;
    if (t < NY) {
        float3 d1, d2;
        deriv_coeffs(y, NY, t, d1, d2);
        g_c1ya[t] = d1.x; g_c1yb[t] = d1.y; g_c1yc[t] = d1.z;
        g_c2ya[t] = mu * d2.x; g_c2yb[t] = mu * d2.y; g_c2yc[t] = mu * d2.z;
    } else if (t < NY + NX) {
        int i = t - NY;
        float3 d1, d2;
        deriv_coeffs(x, NX, i, d1, d2);
        float4 p1, p2;  // permuted: (coeff_TA, coeff_TB, coeff_center, 0)
        if (i == 0) {
            p1 = make_float4(d1.y, d1.z, d1.x, 0.f);
            p2 = make_float4(d2.y, d2.z, d2.x, 0.f);
        } else if (i == NX - 1) {
            p1 = make_float4(d1.x, d1.y, d1.z, 0.f);
            p2 = make_float4(d2.x, d2.y, d2.z, 0.f);
        } else {
            p1 = make_float4(d1.x, d1.z, d1.y, 0.f);
            p2 = make_float4(d2.x, d2.z, d2.y, 0.f);
        }
        g_cx1[i] = p1;
        g_cx2[i] = make_float4(mu * p2.x, mu * p2.y, mu * p2.z, 0.f);
    }
}

// Each thread: 4 consecutive j (float4) x 2 consecutive rows (i0, i0+1).
__global__ __launch_bounds__(128) void rhs_kernel(const float* __restrict__ state,
                                                  float* __restrict__ out) {
    const int j4 = (blockIdx.x * 128 + threadIdx.x) * 4;
    const int i0 = blockIdx.y * 2;
    const int i1 = i0 + 1;
    const int lane = threadIdx.x & 31;

    const float* __restrict__ u = state;
    const float* __restrict__ v = state + (size_t)NX * NY;
    const size_t row0 = (size_t)i0 * NY;
    const size_t row1 = (size_t)i1 * NY;

    // ---- center rows (each is also the other's x-tap) ----
    const float4 uc0 = __ldg((const float4*)(u + row0 + j4));
    const float4 vc0 = __ldg((const float4*)(v + row0 + j4));
    const float4 uc1 = __ldg((const float4*)(u + row1 + j4));
    const float4 vc1 = __ldg((const float4*)(v + row1 + j4));

    // ---- x halo rows (clamped indices at grid edges; unused taps masked by
    //      the block-uniform selects below) ----
    const int rlo = max(i0 - 1, 0);
    const int rhi = min(i0 + 2, NX - 1);
    const float4 uhl = __ldg((const float4*)(u + (size_t)rlo * NY + j4));
    const float4 vhl = __ldg((const float4*)(v + (size_t)rlo * NY + j4));
    const float4 uhh = __ldg((const float4*)(u + (size_t)rhi * NY + j4));
    const float4 vhh = __ldg((const float4*)(v + (size_t)rhi * NY + j4));

    // ---- y halos via warp shuffle; warp-edge lanes fetch scalars ----
    float up0 = __shfl_up_sync(0xffffffffu, uc0.w, 1);
    float vp0 = __shfl_up_sync(0xffffffffu, vc0.w, 1);
    float up1 = __shfl_up_sync(0xffffffffu, uc1.w, 1);
    float vp1 = __shfl_up_sync(0xffffffffu, vc1.w, 1);
    float un0 = __shfl_down_sync(0xffffffffu, uc0.x, 1);
    float vn0 = __shfl_down_sync(0xffffffffu, vc0.x, 1);
    float un1 = __shfl_down_sync(0xffffffffu, uc1.x, 1);
    float vn1 = __shfl_down_sync(0xffffffffu, vc1.x, 1);
    if (lane == 0 && j4 > 0) {
        up0 = __ldg(u + row0 + j4 - 1);
        vp0 = __ldg(v + row0 + j4 - 1);
        up1 = __ldg(u + row1 + j4 - 1);
        vp1 = __ldg(v + row1 + j4 - 1);
    }
    if (lane == 31 && j4 + 4 < NY) {
        un0 = __ldg(u + row0 + j4 + 4);
        vn0 = __ldg(v + row0 + j4 + 4);
        un1 = __ldg(u + row1 + j4 + 4);
        vn1 = __ldg(v + row1 + j4 + 4);
    }

    // ---- y coefficients (SHARED across both rows — key amortization) ----
    const float4 c1a = __ldg((const float4*)(g_c1ya + j4));
    const float4 c1b = __ldg((const float4*)(g_c1yb + j4));
    const float4 c1c = __ldg((const float4*)(g_c1yc + j4));
    const float4 c2a = __ldg((const float4*)(g_c2ya + j4));  // mu-folded
    const float4 c2b = __ldg((const float4*)(g_c2yb + j4));
    const float4 c2c = __ldg((const float4*)(g_c2yc + j4));
    const float4 cxA0 = g_cx1[i0];
    const float4 cxB0 = g_cx2[i0];  // mu-folded
    const float4 cxA1 = g_cx1[i1];
    const float4 cxB1 = g_cx2[i1];

    // ---- x-tap operand selection (block-uniform; matches permuted coeffs) ----
    // row0: interior -> (TA,TB) = (halo_lo, center1) ; i0==0 -> (center1, halo_hi)
    // row1: interior -> (TA,TB) = (center0, halo_hi) ; i1==NX-1 -> (halo_lo, center0)
    const bool lo = (i0 == 0);
    const bool hi = (i1 == NX - 1);
    const float4 TAu0 = lo ? uc1 : uhl, TBu0 = lo ? uhh : uc1;
    const float4 TAv0 = lo ? vc1 : vhl, TBv0 = lo ? vhh : vc1;
    const float4 TAu1 = hi ? uhl : uc0, TBu1 = hi ? uc0 : uhh;
    const float4 TAv1 = hi ? vhl : vc0, TBv1 = hi ? vc0 : vhh;

    // ---- j-boundary tap shifts (k=0 / k=3 only) ----
    const bool jlo = (j4 == 0);
    const bool jhi = (j4 + 4 == NY);
    const float u0L0 = jlo ? uc0.x : up0, u0C0 = jlo ? uc0.y : uc0.x, u0R0 = jlo ? uc0.z : uc0.y;
    const float v0L0 = jlo ? vc0.x : vp0, v0C0 = jlo ? vc0.y : vc0.x, v0R0 = jlo ? vc0.z : vc0.y;
    const float u3L0 = jhi ? uc0.y : uc0.z, u3C0 = jhi ? uc0.z : uc0.w, u3R0 = jhi ? uc0.w : un0;
    const float v3L0 = jhi ? vc0.y : vc0.z, v3C0 = jhi ? vc0.z : vc0.w, v3R0 = jhi ? vc0.w : vn0;
    const float u0L1 = jlo ? uc1.x : up1, u0C1 = jlo ? uc1.y : uc1.x, u0R1 = jlo ? uc1.z : uc1.y;
    const float v0L1 = jlo ? vc1.x : vp1, v0C1 = jlo ? vc1.y : vc1.x, v0R1 = jlo ? vc1.z : vc1.y;
    const float u3L1 = jhi ? uc1.y : uc1.z, u3C1 = jhi ? uc1.z : uc1.w, u3R1 = jhi ? uc1.w : un1;
    const float v3L1 = jhi ? vc1.y : vc1.z, v3C1 = jhi ? vc1.z : vc1.w, v3R1 = jhi ? vc1.w : vn1;

    float4 du0, dv0, du1, dv1;

    // One output point: row r, component cmp.
#define PT(cmp, uL, uC, uR, vL, vC, vR, ucr, vcr, TAu, TBu, TAv, TBv, cx1r, cx2r, dur, dvr) \
    do {                                                                                    \
        const float d1yu = c1a.cmp * (uL) + c1b.cmp * (uC) + c1c.cmp * (uR);                \
        const float m2yu = c2a.cmp * (uL) + c2b.cmp * (uC) + c2c.cmp * (uR);                \
        const float d1yv = c1a.cmp * (vL) + c1b.cmp * (vC) + c1c.cmp * (vR);                \
        const float m2yv = c2a.cmp * (vL) + c2b.cmp * (vC) + c2c.cmp * (vR);                \
        const float d1xu = cx1r.x * TAu.cmp + cx1r.y * TBu.cmp + cx1r.z * ucr.cmp;          \
        const float m2xu = cx2r.x * TAu.cmp + cx2r.y * TBu.cmp + cx2r.z * ucr.cmp;          \
        const float d1xv = cx1r.x * TAv.cmp + cx1r.y * TBv.cmp + cx1r.z * vcr.cmp;          \
        const float m2xv = cx2r.x * TAv.cmp + cx2r.y * TBv.cmp + cx2r.z * vcr.cmp;          \
        dur.cmp = m2yu + m2xu - ucr.cmp * d1xu - vcr.cmp * d1yu + 0.01f;                    \
        dvr.cmp = m2yv + m2xv - ucr.cmp * d1xv - vcr.cmp * d1yv;                            \
    } while (0)

    // Row 0
    PT(x, u0L0, u0C0, u0R0, v0L0, v0C0, v0R0, uc0, vc0, TAu0, TBu0, TAv0, TBv0, cxA0, cxB0, du0, dv0);
    PT(y, uc0.x, uc0.y, uc0.z, vc0.x, vc0.y, vc0.z, uc0, vc0, TAu0, TBu0, TAv0, TBv0, cxA0, cxB0, du0, dv0);
    PT(z, uc0.y, uc0.z, uc0.w, vc0.y, vc0.z, vc0.w, uc0, vc0, TAu0, TBu0, TAv0, TBv0, cxA0, cxB0, du0, dv0);
    PT(w, u3L0, u3C0, u3R0, v3L0, v3C0, v3R0, uc0, vc0, TAu0, TBu0, TAv0, TBv0, cxA0, cxB0, du0, dv0);
    // Row 1
    PT(x, u0L1, u0C1, u0R1, v0L1, v0C1, v0R1, uc1, vc1, TAu1, TBu1, TAv1, TBv1, cxA1, cxB1, du1, dv1);
    PT(y, uc1.x, uc1.y, uc1.z, vc1.x, vc1.y, vc1.z, uc1, vc1, TAu1, TBu1, TAv1, TBv1, cxA1, cxB1, du1, dv1);
    PT(z, uc1.y, uc1.z, uc1.w, vc1.y, vc1.z, vc1.w, uc1, vc1, TAu1, TBu1, TAv1, TBv1, cxA1, cxB1, du1, dv1);
    PT(w, u3L1, u3C1, u3R1, v3L1, v3C1, v3R1, uc1, vc1, TAu1, TBu1, TAv1, TBv1, cxA1, cxB1, du1, dv1);
#undef PT

    // Boundary conditions:
    //   du[:, 0] = du[:, -1] = du[0, :] = 0 ; dv[:, 0] = dv[0, :] = 0
    if (lo) { du0 = make_float4(0.f, 0.f, 0.f, 0.f); dv0 = make_float4(0.f, 0.f, 0.f, 0.f); }
    if (jlo) { du0.x = 0.0f; dv0.x = 0.0f; du1.x = 0.0f; dv1.x = 0.0f; }
    if (jhi) { du0.w = 0.0f; du1.w = 0.0f; }

    const size_t voff = (size_t)NX * NY;
    *(float4*)(out + row0 + j4) = du0;
    *(float4*)(out + voff + row0 + j4) = dv0;
    *(float4*)(out + row1 + j4) = du1;
    *(float4*)(out + voff + row1 + j4) = dv1;
}

// Inputs (metadata order): t[1], state[2*NX*NY], x[NX], y[NY], mu[1]
extern "C" void kernel_launch(void* const* d_in, const int* in_sizes, int n_in,
                              void* d_out, int out_size) {
    const float* state = (const float*)d_in[1];
    const float* x     = (const float*)d_in[2];
    const float* y     = (const float*)d_in[3];
    const float* mu    = (const float*)d_in[4];
    float* out = (float*)d_out;

    {
        int total = NX + NY;
        int threads = 128;
        int blocks = (total + threads - 1) / threads;
        coeff_kernel<<<blocks, threads>>>(x, y, mu);
    }
    {
        dim3 block(128, 1, 1);
        dim3 grid(NY / 512, NX / 2, 1);  // 8 x 1024 blocks, 2 rows x 4 cols per thread
        rhs_kernel<<<grid, block>>>(state, out);
    }
}